// round 1
// baseline (speedup 1.0000x reference)
#include <cuda_runtime.h>
#include <math.h>

// ---------------- problem constants ----------------
#define FDIM   128
#define HID    64
#define MSZ    64
#define NBATCH 8
#define NPTS   65536          // per batch
#define HH     56
#define WW     56
#define HWSZ   (HH*WW)        // 3136

// scratch: F1[b][h][w][j] = sum_c features[b][c][h][w] * W1[c][j]   (img part of layer 1)
__device__ float g_F1[NBATCH * HWSZ * HID];   // 6.4 MB

typedef unsigned long long ull;

__device__ __forceinline__ ull ffma2(ull a, ull b, ull c) {
    ull d;
    asm("fma.rn.f32x2 %0, %1, %2, %3;" : "=l"(d) : "l"(a), "l"(b), "l"(c));
    return d;
}
__device__ __forceinline__ ull pack2(float lo, float hi) {
    ull r;
    asm("mov.b64 %0, {%1, %2};" : "=l"(r) : "f"(lo), "f"(hi));
    return r;
}
__device__ __forceinline__ float2 unpack2(ull v) {
    float2 r;
    asm("mov.b64 {%0, %1}, %2;" : "=f"(r.x), "=f"(r.y) : "l"(v));
    return r;
}

// ======================================================================
// Kernel 1: precompute F1 = features @ W1_img  (per pixel, 64 outputs)
// grid: 196 blocks x 128 threads = 25088 = NBATCH*HWSZ exactly
// ======================================================================
__global__ void __launch_bounds__(128) k_precompute(const float* __restrict__ features,
                                                    const float* __restrict__ W1g) {
    __shared__ float sW[FDIM * HID];          // 32 KB, rows 0..127 of W1
    int tid = threadIdx.x;
    for (int i = tid; i < FDIM * HID; i += 128) sW[i] = W1g[i];
    __syncthreads();

    int pix = blockIdx.x * 128 + tid;         // < 25088
    int b  = pix / HWSZ;
    int hw = pix % HWSZ;

    ull acc[32];
#pragma unroll
    for (int i = 0; i < 32; i++) acc[i] = 0ull;   // bits of (0.f,0.f)

    const float* fptr = features + (size_t)b * FDIM * HWSZ + hw;
    for (int c = 0; c < FDIM; c++) {
        float f = __ldg(fptr + c * HWSZ);
        ull fp = pack2(f, f);
        const ulonglong2* row = (const ulonglong2*)(sW + c * HID);
#pragma unroll
        for (int jj = 0; jj < 16; jj++) {
            ulonglong2 w = row[jj];
            acc[2*jj]   = ffma2(fp, w.x, acc[2*jj]);
            acc[2*jj+1] = ffma2(fp, w.y, acc[2*jj+1]);
        }
    }
    ulonglong2* dst = (ulonglong2*)(g_F1 + (size_t)pix * HID);
#pragma unroll
    for (int jj = 0; jj < 16; jj++) {
        ulonglong2 v; v.x = acc[2*jj]; v.y = acc[2*jj+1];
        dst[jj] = v;
    }
}

// ======================================================================
// Kernel 2: fused decoder. 2 points per thread, f32x2 packed MLP.
// ======================================================================
#define NT 256
// shared-memory float offsets
#define OFF_W1F 0                 // 128 x 64 : [sin rows 0..63][cos rows 64..127]
#define OFF_W2  8192              // 64 x 64
#define OFF_W3  12288             // 64 x 64
#define OFF_W4  16384             // 64
#define OFF_B1  16448
#define OFF_B2  16512
#define OFF_B3  16576
#define OFF_BG  16640             // 64 x 3
#define OFF_ACT 16832             // 64 rows x 512 cols (col per point slot)
#define SMEM_FLOATS (OFF_ACT + 64 * 512)
#define SMEM_BYTES  (SMEM_FLOATS * 4)      // 198400 B

// one bilinear tap: acc[AOFF..AOFF+31] += wt * F1[tap]
#define TAP(IX, IY, WT, AOFF) {                                                        \
    int _cx = min(max((IX), 0), WW-1), _cy = min(max((IY), 0), HH-1);                  \
    float _w = (((IX) >= 0 && (IX) < WW && (IY) >= 0 && (IY) < HH) ? (WT) : 0.f);      \
    ull _wp = pack2(_w, _w);                                                           \
    const ulonglong2* _src = (const ulonglong2*)(g_F1 +                                \
        ((size_t)(bIdx * HWSZ + _cy * WW + _cx)) * HID);                               \
    _Pragma("unroll")                                                                  \
    for (int jj = 0; jj < 16; jj++) {                                                  \
        ulonglong2 _v = _src[jj];                                                      \
        acc[(AOFF)+2*jj]   = ffma2(_wp, _v.x, acc[(AOFF)+2*jj]);                       \
        acc[(AOFF)+2*jj+1] = ffma2(_wp, _v.y, acc[(AOFF)+2*jj+1]);                     \
    }                                                                                  \
}

// projection + bilinear sample for one point
#define BILIN(PX, PY, PZ, AOFF) do {                                                   \
    float cx = r0*(PX) + r1*(PY) + r2 *(PZ) + r3;                                      \
    float cy = r4*(PX) + r5*(PY) + r6 *(PZ) + r7;                                      \
    float cz = r8*(PX) + r9*(PY) + r10*(PZ) + r11;                                     \
    float ix = k0*cx + k1*cy + k2*cz;                                                  \
    float iy = k3*cx + k4*cy + k5*cz;                                                  \
    float iz = k6*cx + k7*cy + k8*cz;                                                  \
    float zz = iz + 1e-8f;                                                             \
    float u = ix / zz, v = iy / zz;                                                    \
    float valid = (iz > 0.f) ? 1.f : 0.f;                                              \
    float un = (2.f*u + 1.f) / (float)WW - 1.f;                                        \
    float vn = (2.f*v + 1.f) / (float)HH - 1.f;                                        \
    float xx = ((un + 1.f) * (float)WW - 1.f) * 0.5f;                                  \
    float yy = ((vn + 1.f) * (float)HH - 1.f) * 0.5f;                                  \
    float xf = floorf(xx), yf = floorf(yy);                                            \
    float fx = xx - xf, fy = yy - yf;                                                  \
    int x0i = (int)xf, y0i = (int)yf;                                                  \
    TAP(x0i,     y0i,     (1.f-fx)*(1.f-fy)*valid, AOFF)                               \
    TAP(x0i + 1, y0i,     fx      *(1.f-fy)*valid, AOFF)                               \
    TAP(x0i,     y0i + 1, (1.f-fx)*fy      *valid, AOFF)                               \
    TAP(x0i + 1, y0i + 1, fx      *fy      *valid, AOFF)                               \
} while (0)

// relu + store acc (both points) to the smem activation staging buffer
#define STORE_RELU() {                                                                 \
    _Pragma("unroll")                                                                  \
    for (int i = 0; i < 32; i++) {                                                     \
        float2 f = unpack2(acc[i]);                                                    \
        actc[(2*i)   * 512]      = fmaxf(f.x, 0.f);                                    \
        actc[(2*i+1) * 512]      = fmaxf(f.y, 0.f);                                    \
        float2 g = unpack2(acc[32 + i]);                                               \
        actc[(2*i)   * 512 + NT] = fmaxf(g.x, 0.f);                                    \
        actc[(2*i+1) * 512 + NT] = fmaxf(g.y, 0.f);                                    \
    }                                                                                  \
}

// 64x64 dense layer from staging buffer, weight row amortized over 2 points
#define LAYER(WOFF, BOFF) {                                                            \
    const ulonglong2* _bv = (const ulonglong2*)(sm + (BOFF));                          \
    _Pragma("unroll")                                                                  \
    for (int jj = 0; jj < 16; jj++) {                                                  \
        ulonglong2 _v = _bv[jj];                                                       \
        acc[2*jj] = _v.x;      acc[2*jj+1] = _v.y;                                     \
        acc[32+2*jj] = _v.x;   acc[32+2*jj+1] = _v.y;                                  \
    }                                                                                  \
    for (int kk = 0; kk < 64; kk++) {                                                  \
        float a0 = actc[kk * 512];                                                     \
        float a1 = actc[kk * 512 + NT];                                                \
        ull a0p = pack2(a0, a0), a1p = pack2(a1, a1);                                  \
        const ulonglong2* _row = (const ulonglong2*)(sm + (WOFF) + kk * 64);           \
        _Pragma("unroll")                                                              \
        for (int jj = 0; jj < 16; jj++) {                                              \
            ulonglong2 w = _row[jj];                                                   \
            acc[2*jj]      = ffma2(a0p, w.x, acc[2*jj]);                               \
            acc[2*jj+1]    = ffma2(a0p, w.y, acc[2*jj+1]);                             \
            acc[32+2*jj]   = ffma2(a1p, w.x, acc[32+2*jj]);                            \
            acc[32+2*jj+1] = ffma2(a1p, w.y, acc[32+2*jj+1]);                          \
        }                                                                              \
    }                                                                                  \
}

__global__ void __launch_bounds__(NT, 1) k_decoder(
    const float* __restrict__ pts, const float* __restrict__ Km,
    const float* __restrict__ RTg, const float* __restrict__ Bgg,
    const float* __restrict__ W1g, const float* __restrict__ b1g,
    const float* __restrict__ W2g, const float* __restrict__ b2g,
    const float* __restrict__ W3g, const float* __restrict__ b3g,
    const float* __restrict__ W4g, const float* __restrict__ b4g,
    float* __restrict__ out)
{
    extern __shared__ float sm[];
    int tid = threadIdx.x;

    // cooperative weight load (W1 rows 128..255 = [sin;cos] block, contiguous)
    for (int i = tid; i < 8192; i += NT) sm[OFF_W1F + i] = W1g[8192 + i];
    for (int i = tid; i < 4096; i += NT) sm[OFF_W2 + i] = W2g[i];
    for (int i = tid; i < 4096; i += NT) sm[OFF_W3 + i] = W3g[i];
    for (int i = tid; i < 64;   i += NT) {
        sm[OFF_W4 + i] = W4g[i];
        sm[OFF_B1 + i] = b1g[i];
        sm[OFF_B2 + i] = b2g[i];
        sm[OFF_B3 + i] = b3g[i];
    }
    for (int i = tid; i < 192; i += NT) sm[OFF_BG + i] = Bgg[i];
    __syncthreads();

    int p0 = blockIdx.x * (2 * NT) + tid;     // point 0 for this thread
    int p1 = p0 + NT;                          // point 1 (same batch: 65536 % 512 == 0)
    int bIdx = p0 >> 16;                       // batch index

    // camera matrices (uniform across block -> L1 broadcast)
    const float* rtb = RTg + bIdx * 12;
    const float* kb  = Km  + bIdx * 9;
    float r0 = rtb[0], r1 = rtb[1], r2 = rtb[2],  r3 = rtb[3];
    float r4 = rtb[4], r5 = rtb[5], r6 = rtb[6],  r7 = rtb[7];
    float r8 = rtb[8], r9 = rtb[9], r10 = rtb[10], r11 = rtb[11];
    float k0 = kb[0], k1 = kb[1], k2 = kb[2];
    float k3 = kb[3], k4 = kb[4], k5 = kb[5];
    float k6 = kb[6], k7 = kb[7], k8 = kb[8];

    const float* pp0 = pts + (size_t)p0 * 3;
    const float* pp1 = pts + (size_t)p1 * 3;
    float px0 = pp0[0], py0 = pp0[1], pz0 = pp0[2];
    float px1 = pp1[0], py1 = pp1[1], pz1 = pp1[2];

    // ---- layer 1: acc = b1 + bilinear(F1) + fourier @ W1f ----
    ull acc[64];                               // [0..31] point0, [32..63] point1 (pairs of outputs)
    {
        const ulonglong2* bv = (const ulonglong2*)(sm + OFF_B1);
#pragma unroll
        for (int jj = 0; jj < 16; jj++) {
            ulonglong2 v = bv[jj];
            acc[2*jj] = v.x;      acc[2*jj+1] = v.y;
            acc[32+2*jj] = v.x;   acc[32+2*jj+1] = v.y;
        }
    }

    BILIN(px0, py0, pz0, 0);
    BILIN(px1, py1, pz1, 32);

    // fourier features: theta_m = 2*pi*(p . Bg[m]); sin/cos via sincospif(2t)
    const float* bg = sm + OFF_BG;
    for (int m = 0; m < 64; m++) {
        float g0 = bg[3*m], g1 = bg[3*m+1], g2 = bg[3*m+2];
        float t0 = px0*g0 + py0*g1 + pz0*g2;
        float t1 = px1*g0 + py1*g1 + pz1*g2;
        float s0, c0, s1, c1;
        sincospif(2.f * t0, &s0, &c0);
        sincospif(2.f * t1, &s1, &c1);
        ull s0p = pack2(s0, s0), c0p = pack2(c0, c0);
        ull s1p = pack2(s1, s1), c1p = pack2(c1, c1);
        const ulonglong2* rs = (const ulonglong2*)(sm + OFF_W1F + m * 64);
        const ulonglong2* rc = (const ulonglong2*)(sm + OFF_W1F + (64 + m) * 64);
#pragma unroll
        for (int jj = 0; jj < 16; jj++) {
            ulonglong2 ws = rs[jj];
            ulonglong2 wc = rc[jj];
            acc[2*jj]      = ffma2(s0p, ws.x, acc[2*jj]);
            acc[2*jj+1]    = ffma2(s0p, ws.y, acc[2*jj+1]);
            acc[32+2*jj]   = ffma2(s1p, ws.x, acc[32+2*jj]);
            acc[32+2*jj+1] = ffma2(s1p, ws.y, acc[32+2*jj+1]);
            acc[2*jj]      = ffma2(c0p, wc.x, acc[2*jj]);
            acc[2*jj+1]    = ffma2(c0p, wc.y, acc[2*jj+1]);
            acc[32+2*jj]   = ffma2(c1p, wc.x, acc[32+2*jj]);
            acc[32+2*jj+1] = ffma2(c1p, wc.y, acc[32+2*jj+1]);
        }
    }

    float* actc = sm + OFF_ACT + tid;          // thread-private column, stride 512

    STORE_RELU();          // h1 -> staging
    LAYER(OFF_W2, OFF_B2); // h2 = h1 @ W2 + b2
    STORE_RELU();          // h2 -> staging (own column only: no sync needed)
    LAYER(OFF_W3, OFF_B3); // h3 = h2 @ W3 + b3

    // final: relu(h3) . W4 + b4, h3 stays in registers
    float bias4 = __ldg(b4g);
    const float* w4 = sm + OFF_W4;
    float o0 = 0.f, o1 = 0.f;
#pragma unroll
    for (int i = 0; i < 32; i++) {
        float2 a = unpack2(acc[i]);
        o0 += fmaxf(a.x, 0.f) * w4[2*i] + fmaxf(a.y, 0.f) * w4[2*i+1];
        float2 g = unpack2(acc[32 + i]);
        o1 += fmaxf(g.x, 0.f) * w4[2*i] + fmaxf(g.y, 0.f) * w4[2*i+1];
    }
    out[p0] = o0 + bias4;
    out[p1] = o1 + bias4;
}

// ======================================================================
extern "C" void kernel_launch(void* const* d_in, const int* in_sizes, int n_in,
                              void* d_out, int out_size) {
    const float* features = (const float*)d_in[0];
    const float* points   = (const float*)d_in[1];
    const float* kmat     = (const float*)d_in[2];
    const float* rt       = (const float*)d_in[3];
    const float* Bg       = (const float*)d_in[4];
    const float* W1       = (const float*)d_in[5];
    const float* b1       = (const float*)d_in[6];
    const float* W2       = (const float*)d_in[7];
    const float* b2       = (const float*)d_in[8];
    const float* W3       = (const float*)d_in[9];
    const float* b3       = (const float*)d_in[10];
    const float* W4       = (const float*)d_in[11];
    const float* b4       = (const float*)d_in[12];
    float* out = (float*)d_out;

    cudaFuncSetAttribute(k_decoder, cudaFuncAttributeMaxDynamicSharedMemorySize, SMEM_BYTES);

    k_precompute<<<196, 128>>>(features, W1);
    k_decoder<<<(NBATCH * NPTS) / (2 * NT), NT, SMEM_BYTES>>>(
        points, kmat, rt, Bg, W1, b1, W2, b2, W3, b3, W4, b4, out);
}